// round 15
// baseline (speedup 1.0000x reference)
#include <cuda_runtime.h>

#define NN 100000
#define NE 1600000
#define NG 256
#define CAP 64          // padded CSR capacity per node (Poisson(16): overflow ~1e-20)
#define CAPSH 6
#define FILL_BLOCKS 1563   // ceil((NE/4)/256)
#define PREP_BLOCKS 391    // ceil(NN/256)

// Scratch (static __device__ arrays; zero-initialized at module load; no allocation)
__device__ float g_bufA[NN * 16];    // L0 output
__device__ float g_bufB[NN * 32];    // L1 output
__device__ float g_agg[NN * 32];     // raw neighbor sums (16w for L1, 32w for L2)
__device__ float g_tbuf[NN * 16];    // t0 (16w); later t3 (float2/node)
__device__ float g_rbuf[NN * 16];    // r0 (16w); later r3 (float2/node)
__device__ int   g_pos[NN];          // degree counter; re-zeroed by k_g2pool each call
__device__ int   g_csr[NN * CAP];    // padded CSR
__device__ float g_pool[NG * 2];     // zeroed by k_update2 block 0 each call
__device__ float g_gcnt[NG];
__device__ int   g_done;             // self-resetting

// ---------------- fused CSR build + L0 prep (independent work, one launch) ----------------

__global__ void __launch_bounds__(256) k_fillprep(
        const int* __restrict__ src, const int* __restrict__ dst,
        const float* __restrict__ x,
        const float* __restrict__ Wl, const float* __restrict__ bl,
        const float* __restrict__ Wr) {
    __shared__ float sWl[56 * 16];
    __shared__ float sWr[56 * 16];
    __shared__ float sb[16];
    if (blockIdx.x < FILL_BLOCKS) {
        const int Q = NE / 4;
        int tbase = blockIdx.x * blockDim.x + threadIdx.x;
        if (tbase >= Q) return;
        int e0 = tbase, e1 = tbase + Q, e2 = tbase + 2 * Q, e3 = tbase + 3 * Q;
        int d0 = dst[e0], d1 = dst[e1], d2 = dst[e2], d3 = dst[e3];
        int s0 = src[e0], s1 = src[e1], s2 = src[e2], s3 = src[e3];
        int p0 = atomicAdd(&g_pos[d0], 1);
        int p1 = atomicAdd(&g_pos[d1], 1);
        int p2 = atomicAdd(&g_pos[d2], 1);
        int p3 = atomicAdd(&g_pos[d3], 1);
        if (p0 < CAP) g_csr[(d0 << CAPSH) + p0] = s0;
        if (p1 < CAP) g_csr[(d1 << CAPSH) + p1] = s1;
        if (p2 < CAP) g_csr[(d2 << CAPSH) + p2] = s2;
        if (p3 < CAP) g_csr[(d3 << CAPSH) + p3] = s3;
    } else {
        for (int idx = threadIdx.x; idx < 56 * 16; idx += blockDim.x) {
            sWl[idx] = Wl[idx];
            sWr[idx] = Wr[idx];
        }
        if (threadIdx.x < 16) sb[threadIdx.x] = bl[threadIdx.x];
        __syncthreads();
        int i = (blockIdx.x - FILL_BLOCKS) * blockDim.x + threadIdx.x;
        if (i >= NN) return;
        float al[16], ar[16];
#pragma unroll
        for (int j = 0; j < 16; j++) { al[j] = 0.f; ar[j] = sb[j]; }
#pragma unroll 2
        for (int k = 0; k < 56; k++) {
            float hv = x[(size_t)i * 56 + k];
#pragma unroll
            for (int j = 0; j < 16; j++) {
                al[j] += hv * sWl[k * 16 + j];
                ar[j] += hv * sWr[k * 16 + j];
            }
        }
#pragma unroll
        for (int j = 0; j < 16; j++) {
            g_tbuf[(size_t)i * 16 + j] = al[j];
            g_rbuf[(size_t)i * 16 + j] = ar[j];
        }
    }
}

// ---------------- gather cores (paired-slot, MLP 2) ----------------

__device__ __forceinline__ float4 gather16_core(const float* __restrict__ h,
                                                int gw, int lane, int degc) {
    int c4 = lane & 3;
    int slot = lane >> 2;
    int s0 = gw << CAPSH;
    float4 acc = make_float4(0.f, 0.f, 0.f, 0.f);
    int lim = min(degc, 32);
    int si = (lane < lim) ? g_csr[s0 + lane] : 0;
    for (int jb = 0; jb < lim; jb += 16) {
        int j0 = jb + slot;
        int j1 = jb + 8 + slot;
        int sA = __shfl_sync(0xffffffffu, si, j0);
        int sB = __shfl_sync(0xffffffffu, si, j1);
        if (j0 < lim) {
            float4 v = *reinterpret_cast<const float4*>(h + (size_t)sA * 16 + c4 * 4);
            acc.x += v.x; acc.y += v.y; acc.z += v.z; acc.w += v.w;
        }
        if (j1 < lim) {
            float4 v = *reinterpret_cast<const float4*>(h + (size_t)sB * 16 + c4 * 4);
            acc.x += v.x; acc.y += v.y; acc.z += v.z; acc.w += v.w;
        }
    }
    if (degc > 32) {
        int lim2 = degc - 32;
        int si2 = (lane < lim2) ? g_csr[s0 + 32 + lane] : 0;
        for (int jb = 0; jb < lim2; jb += 16) {
            int j0 = jb + slot;
            int j1 = jb + 8 + slot;
            int sA = __shfl_sync(0xffffffffu, si2, j0);
            int sB = __shfl_sync(0xffffffffu, si2, j1);
            if (j0 < lim2) {
                float4 v = *reinterpret_cast<const float4*>(h + (size_t)sA * 16 + c4 * 4);
                acc.x += v.x; acc.y += v.y; acc.z += v.z; acc.w += v.w;
            }
            if (j1 < lim2) {
                float4 v = *reinterpret_cast<const float4*>(h + (size_t)sB * 16 + c4 * 4);
                acc.x += v.x; acc.y += v.y; acc.z += v.z; acc.w += v.w;
            }
        }
    }
#pragma unroll
    for (int m = 4; m < 32; m <<= 1) {
        acc.x += __shfl_xor_sync(0xffffffffu, acc.x, m);
        acc.y += __shfl_xor_sync(0xffffffffu, acc.y, m);
        acc.z += __shfl_xor_sync(0xffffffffu, acc.z, m);
        acc.w += __shfl_xor_sync(0xffffffffu, acc.w, m);
    }
    return acc;
}

__device__ __forceinline__ float4 gather32_core(const float* __restrict__ h,
                                                int gw, int lane, int degc) {
    int c4 = lane & 7;
    int slot = lane >> 3;
    int s0 = gw << CAPSH;
    float4 acc = make_float4(0.f, 0.f, 0.f, 0.f);
    int lim = min(degc, 32);
    int si = (lane < lim) ? g_csr[s0 + lane] : 0;
    for (int jb = 0; jb < lim; jb += 8) {
        int j0 = jb + slot;
        int j1 = jb + 4 + slot;
        int sA = __shfl_sync(0xffffffffu, si, j0);
        int sB = __shfl_sync(0xffffffffu, si, j1);
        if (j0 < lim) {
            float4 v = *reinterpret_cast<const float4*>(h + (size_t)sA * 32 + c4 * 4);
            acc.x += v.x; acc.y += v.y; acc.z += v.z; acc.w += v.w;
        }
        if (j1 < lim) {
            float4 v = *reinterpret_cast<const float4*>(h + (size_t)sB * 32 + c4 * 4);
            acc.x += v.x; acc.y += v.y; acc.z += v.z; acc.w += v.w;
        }
    }
    if (degc > 32) {
        int lim2 = degc - 32;
        int si2 = (lane < lim2) ? g_csr[s0 + 32 + lane] : 0;
        for (int jb = 0; jb < lim2; jb += 8) {
            int j0 = jb + slot;
            int j1 = jb + 4 + slot;
            int sA = __shfl_sync(0xffffffffu, si2, j0);
            int sB = __shfl_sync(0xffffffffu, si2, j1);
            if (j0 < lim2) {
                float4 v = *reinterpret_cast<const float4*>(h + (size_t)sA * 32 + c4 * 4);
                acc.x += v.x; acc.y += v.y; acc.z += v.z; acc.w += v.w;
            }
            if (j1 < lim2) {
                float4 v = *reinterpret_cast<const float4*>(h + (size_t)sB * 32 + c4 * 4);
                acc.x += v.x; acc.y += v.y; acc.z += v.z; acc.w += v.w;
            }
        }
    }
#pragma unroll
    for (int m = 8; m < 32; m <<= 1) {
        acc.x += __shfl_xor_sync(0xffffffffu, acc.x, m);
        acc.y += __shfl_xor_sync(0xffffffffu, acc.y, m);
        acc.z += __shfl_xor_sync(0xffffffffu, acc.z, m);
        acc.w += __shfl_xor_sync(0xffffffffu, acc.w, m);
    }
    return acc;
}

// ---------------- L0 gather (pre, W=16): bufA = relu(agg/deg + r0) ----------------

__global__ void k_g16pre() {
    int gw = (blockIdx.x * blockDim.x + threadIdx.x) >> 5;
    if (gw >= NN) return;
    int lane = threadIdx.x & 31;
    int deg = g_pos[gw];
    float4 acc = gather16_core(g_tbuf, gw, lane, min(deg, CAP));
    if (lane < 4) {
        int c4 = lane;
        float inv = 1.f / fmaxf((float)deg, 1.f);
        float4 rv = *reinterpret_cast<const float4*>(g_rbuf + (size_t)gw * 16 + c4 * 4);
        float4 o;
        o.x = fmaxf(acc.x * inv + rv.x, 0.f);
        o.y = fmaxf(acc.y * inv + rv.y, 0.f);
        o.z = fmaxf(acc.z * inv + rv.z, 0.f);
        o.w = fmaxf(acc.w * inv + rv.w, 0.f);
        *reinterpret_cast<float4*>(g_bufA + (size_t)gw * 16 + c4 * 4) = o;
    }
}

// ---------------- L1 gather-only ----------------

__global__ void k_g16agg() {
    int gw = (blockIdx.x * blockDim.x + threadIdx.x) >> 5;
    if (gw >= NN) return;
    int lane = threadIdx.x & 31;
    float4 acc = gather16_core(g_bufA, gw, lane, min(g_pos[gw], CAP));
    if (lane < 4)
        *reinterpret_cast<float4*>(g_agg + (size_t)gw * 16 + lane * 4) = acc;
}

// ---------------- L1 update: smem-staged, 2 threads/node x 16 outputs ----------------
// Block: 256 threads = 128 nodes. Stage agg+bufA rows coalesced (stride-17 pad).

__global__ void __launch_bounds__(256) k_update1(const float* __restrict__ Wl,
                                                 const float* __restrict__ bl,
                                                 const float* __restrict__ Wr) {
    __shared__ float sWl[16 * 32];
    __shared__ float sWr[16 * 32];
    __shared__ float sb[32];
    __shared__ float sAgg[128 * 17];
    __shared__ float sH[128 * 17];
    for (int idx = threadIdx.x; idx < 16 * 32; idx += 256) {
        sWl[idx] = Wl[idx];
        sWr[idx] = Wr[idx];
    }
    if (threadIdx.x < 32) sb[threadIdx.x] = bl[threadIdx.x];
    int nb0 = blockIdx.x * 128;
    for (int idx = threadIdx.x; idx < 128 * 16; idx += 256) {
        int node = idx >> 4, k = idx & 15;
        size_t gidx = (size_t)(nb0 + node) * 16 + k;
        bool ok = (nb0 + node) < NN;
        sAgg[node * 17 + k] = ok ? g_agg[gidx] : 0.f;
        sH[node * 17 + k] = ok ? g_bufA[gidx] : 0.f;
    }
    __syncthreads();
    int nl = threadIdx.x >> 1;        // local node 0..127
    int sub = threadIdx.x & 1;        // output half
    int i = nb0 + nl;
    if (i >= NN) return;
    float inv = 1.f / fmaxf((float)g_pos[i], 1.f);
    float acc[16];
#pragma unroll
    for (int j = 0; j < 16; j++) acc[j] = sb[sub * 16 + j];
#pragma unroll 4
    for (int k = 0; k < 16; k++) {
        float a = sAgg[nl * 17 + k] * inv;
        float hv = sH[nl * 17 + k];
#pragma unroll
        for (int j = 0; j < 16; j++)
            acc[j] += a * sWl[k * 32 + sub * 16 + j] + hv * sWr[k * 32 + sub * 16 + j];
    }
    float* outp = g_bufB + (size_t)i * 32 + sub * 16;
#pragma unroll
    for (int j4 = 0; j4 < 4; j4++) {
        float4 o;
        o.x = fmaxf(acc[j4 * 4 + 0], 0.f);
        o.y = fmaxf(acc[j4 * 4 + 1], 0.f);
        o.z = fmaxf(acc[j4 * 4 + 2], 0.f);
        o.w = fmaxf(acc[j4 * 4 + 3], 0.f);
        *reinterpret_cast<float4*>(outp + j4 * 4) = o;
    }
}

// ---------------- L2 gather-only ----------------

__global__ void k_g32agg() {
    int gw = (blockIdx.x * blockDim.x + threadIdx.x) >> 5;
    if (gw >= NN) return;
    int lane = threadIdx.x & 31;
    float4 acc = gather32_core(g_bufB, gw, lane, min(g_pos[gw], CAP));
    if (lane < 8)
        *reinterpret_cast<float4*>(g_agg + (size_t)gw * 32 + lane * 4) = acc;
}

// ---------------- L2 update: smem-staged, 4 threads/node x 16 outputs, fused L3 prep ----------------
// Block: 256 threads = 64 nodes. Stage agg+bufB rows coalesced (stride-33 pad).

__global__ void __launch_bounds__(256) k_update2(const float* __restrict__ Wl,
                                                 const float* __restrict__ bl,
                                                 const float* __restrict__ Wr,
                                                 const float* __restrict__ Wl3,
                                                 const float* __restrict__ bl3,
                                                 const float* __restrict__ Wr3) {
    __shared__ float sWl[32 * 64];
    __shared__ float sWr[32 * 64];
    __shared__ float sb[64];
    __shared__ float sWl3[64 * 2];
    __shared__ float sWr3[64 * 2];
    __shared__ float sb3[2];
    __shared__ float sAgg[64 * 33];
    __shared__ float sH[64 * 33];
    for (int idx = threadIdx.x; idx < 32 * 64; idx += 256) {
        sWl[idx] = Wl[idx];
        sWr[idx] = Wr[idx];
    }
    if (threadIdx.x < 64) sb[threadIdx.x] = bl[threadIdx.x];
    if (threadIdx.x < 128) { sWl3[threadIdx.x] = Wl3[threadIdx.x]; sWr3[threadIdx.x] = Wr3[threadIdx.x]; }
    if (threadIdx.x < 2) sb3[threadIdx.x] = bl3[threadIdx.x];
    if (blockIdx.x == 0) {
        for (int idx = threadIdx.x; idx < NG * 2; idx += 256) g_pool[idx] = 0.f;
        for (int idx = threadIdx.x; idx < NG; idx += 256) g_gcnt[idx] = 0.f;
    }
    int nb0 = blockIdx.x * 64;
    for (int idx = threadIdx.x; idx < 64 * 32; idx += 256) {
        int node = idx >> 5, k = idx & 31;
        size_t gidx = (size_t)(nb0 + node) * 32 + k;
        bool ok = (nb0 + node) < NN;
        sAgg[node * 33 + k] = ok ? g_agg[gidx] : 0.f;
        sH[node * 33 + k] = ok ? g_bufB[gidx] : 0.f;
    }
    __syncthreads();
    int nl = threadIdx.x >> 2;        // local node 0..63
    int sub = threadIdx.x & 3;        // output quarter (16 channels)
    int i = nb0 + nl;
    float t3p0 = 0.f, t3p1 = 0.f, r3p0 = 0.f, r3p1 = 0.f;
    if (i < NN) {
        float inv = 1.f / fmaxf((float)g_pos[i], 1.f);
        float acc[16];
#pragma unroll
        for (int j = 0; j < 16; j++) acc[j] = sb[sub * 16 + j];
#pragma unroll 4
        for (int k = 0; k < 32; k++) {
            float a = sAgg[nl * 33 + k] * inv;
            float hv = sH[nl * 33 + k];
#pragma unroll
            for (int j = 0; j < 16; j++)
                acc[j] += a * sWl[k * 64 + sub * 16 + j] + hv * sWr[k * 64 + sub * 16 + j];
        }
#pragma unroll
        for (int j = 0; j < 16; j++) {
            float h3 = fmaxf(acc[j], 0.f);
            int ch = sub * 16 + j;
            t3p0 += h3 * sWl3[ch * 2 + 0];
            t3p1 += h3 * sWl3[ch * 2 + 1];
            r3p0 += h3 * sWr3[ch * 2 + 0];
            r3p1 += h3 * sWr3[ch * 2 + 1];
        }
    }
    // reduce across the 4 lanes of this node (consecutive lanes; xor 1,2)
#pragma unroll
    for (int m = 1; m < 4; m <<= 1) {
        t3p0 += __shfl_xor_sync(0xffffffffu, t3p0, m);
        t3p1 += __shfl_xor_sync(0xffffffffu, t3p1, m);
        r3p0 += __shfl_xor_sync(0xffffffffu, r3p0, m);
        r3p1 += __shfl_xor_sync(0xffffffffu, r3p1, m);
    }
    if (i < NN && sub == 0) {
        reinterpret_cast<float2*>(g_tbuf)[i] = make_float2(t3p0, t3p1);
        reinterpret_cast<float2*>(g_rbuf)[i] = make_float2(r3p0 + sb3[0], r3p1 + sb3[1]);
    }
}

// ---------------- L3 gather + pool (2 nodes/warp) + g_pos reset + last-block softmax ----------------

__global__ void __launch_bounds__(256) k_g2pool(const int* __restrict__ batch,
                                                float* __restrict__ out,
                                                int nblocks) {
    int w = (blockIdx.x * blockDim.x + threadIdx.x) >> 5;
    int lane = threadIdx.x & 31;
    int half = lane >> 4;
    int sub = lane & 15;
    int gw = w * 2 + half;
    float ax = 0.f, ay = 0.f;
    int deg = 0;
    if (gw < NN) {
        deg = g_pos[gw];
        int degc = min(deg, CAP);
        int s0 = gw << CAPSH;
        const float2* tv = reinterpret_cast<const float2*>(g_tbuf);
        for (int e = sub; e < degc; e += 16) {
            float2 v = tv[g_csr[s0 + e]];
            ax += v.x; ay += v.y;
        }
    }
#pragma unroll
    for (int m = 1; m < 16; m <<= 1) {
        ax += __shfl_xor_sync(0xffffffffu, ax, m);
        ay += __shfl_xor_sync(0xffffffffu, ay, m);
    }
    if (gw < NN && sub == 0) {
        g_pos[gw] = 0;  // reset degree counter for the next call
        float inv = 1.f / fmaxf((float)deg, 1.f);
        float2 rv = reinterpret_cast<const float2*>(g_rbuf)[gw];
        float hx = fmaxf(ax * inv + rv.x, 0.f);
        float hy = fmaxf(ay * inv + rv.y, 0.f);
        int g = batch[gw];
        atomicAdd(&g_pool[2 * g + 0], hx);
        atomicAdd(&g_pool[2 * g + 1], hy);
        atomicAdd(&g_gcnt[g], 1.f);
    }
    __shared__ int last;
    __syncthreads();
    if (threadIdx.x == 0) {
        __threadfence();
        int v = atomicAdd(&g_done, 1);
        last = (v == nblocks - 1) ? 1 : 0;
    }
    __syncthreads();
    if (last) {
        __threadfence();
        int g = threadIdx.x;
        if (g < NG) {
            float c = fmaxf(g_gcnt[g], 1.f);
            float a = g_pool[2 * g + 0] / c;
            float b = g_pool[2 * g + 1] / c;
            float m = fmaxf(a, b);
            float ea = expf(a - m);
            float eb = expf(b - m);
            float s = ea + eb;
            out[2 * g + 0] = ea / s;
            out[2 * g + 1] = eb / s;
        }
        if (threadIdx.x == 0) g_done = 0;
    }
}

extern "C" void kernel_launch(void* const* d_in, const int* in_sizes, int n_in,
                              void* d_out, int out_size) {
    const float* x = (const float*)d_in[0];
    const int* ei = (const int*)d_in[1];
    const int* batch = (const int*)d_in[2];
    const float* Wl0 = (const float*)d_in[3];
    const float* bl0 = (const float*)d_in[4];
    const float* Wr0 = (const float*)d_in[5];
    const float* Wl1 = (const float*)d_in[6];
    const float* bl1 = (const float*)d_in[7];
    const float* Wr1 = (const float*)d_in[8];
    const float* Wl2 = (const float*)d_in[9];
    const float* bl2 = (const float*)d_in[10];
    const float* Wr2 = (const float*)d_in[11];
    const float* Wl3 = (const float*)d_in[12];
    const float* bl3 = (const float*)d_in[13];
    const float* Wr3 = (const float*)d_in[14];
    float* out = (float*)d_out;

    const int* src = ei;
    const int* dst = ei + NE;

    const int TB = 256;
    auto nb = [](long n, int tb) { return (int)((n + tb - 1) / tb); };
    const int GATHER_GRID = nb((long)NN * 32, TB);       // warp per node (12500)
    const int POOL_GRID = nb((long)NN * 16, TB);         // 2 nodes per warp (6250)

    // 1. fused CSR build + L0 prep
    k_fillprep<<<FILL_BLOCKS + PREP_BLOCKS, TB>>>(src, dst, x, Wl0, bl0, Wr0);
    // 2. L0 gather (pre)
    k_g16pre<<<GATHER_GRID, TB>>>();
    // 3. L1 gather-only
    k_g16agg<<<GATHER_GRID, TB>>>();
    // 4. L1 update (smem-staged, 2 threads/node)
    k_update1<<<nb(NN, 128), TB>>>(Wl1, bl1, Wr1);
    // 5. L2 gather-only
    k_g32agg<<<GATHER_GRID, TB>>>();
    // 6. L2 update (smem-staged, 4 threads/node) + fused L3 prep + pool-zero
    k_update2<<<nb(NN, 64), TB>>>(Wl2, bl2, Wr2, Wl3, bl3, Wr3);
    // 7. L3 gather + pool + softmax
    k_g2pool<<<POOL_GRID, TB>>>(batch, out, POOL_GRID);
}

// round 16
// speedup vs baseline: 1.1119x; 1.1119x over previous
#include <cuda_runtime.h>

#define NN 100000
#define NE 1600000
#define NG 256
#define CAP 64          // padded CSR capacity per node (Poisson(16): overflow ~1e-20)
#define CAPSH 6
#define FILL_BLOCKS 1563   // ceil((NE/4)/256)
#define PREP_BLOCKS 391    // ceil(NN/256)

// Scratch (static __device__ arrays; zero-initialized at module load; no allocation)
__device__ float g_bufA[NN * 16];    // L0 output
__device__ float g_bufB[NN * 32];    // L1 output
__device__ float g_agg[NN * 32];     // raw neighbor sums (16w for L1, 32w for L2)
__device__ float g_tbuf[NN * 16];    // t0 (16w); later t3 (float2/node)
__device__ float g_rbuf[NN * 16];    // r0 (16w); later r3 (float2/node)
__device__ int   g_pos[NN];          // degree counter; re-zeroed by k_g2pool each call
__device__ int   g_csr[NN * CAP];    // padded CSR
__device__ float g_pool[NG * 2];     // zeroed by k_update2 block 0 each call
__device__ float g_gcnt[NG];
__device__ int   g_done;             // self-resetting

// ---------------- fused CSR build + L0 prep (independent work, one launch) ----------------

__global__ void __launch_bounds__(256) k_fillprep(
        const int* __restrict__ src, const int* __restrict__ dst,
        const float* __restrict__ x,
        const float* __restrict__ Wl, const float* __restrict__ bl,
        const float* __restrict__ Wr) {
    __shared__ float sWl[56 * 16];
    __shared__ float sWr[56 * 16];
    __shared__ float sb[16];
    if (blockIdx.x < FILL_BLOCKS) {
        const int Q = NE / 4;
        int tbase = blockIdx.x * blockDim.x + threadIdx.x;
        if (tbase >= Q) return;
        int e0 = tbase, e1 = tbase + Q, e2 = tbase + 2 * Q, e3 = tbase + 3 * Q;
        int d0 = dst[e0], d1 = dst[e1], d2 = dst[e2], d3 = dst[e3];
        int s0 = src[e0], s1 = src[e1], s2 = src[e2], s3 = src[e3];
        int p0 = atomicAdd(&g_pos[d0], 1);
        int p1 = atomicAdd(&g_pos[d1], 1);
        int p2 = atomicAdd(&g_pos[d2], 1);
        int p3 = atomicAdd(&g_pos[d3], 1);
        if (p0 < CAP) g_csr[(d0 << CAPSH) + p0] = s0;
        if (p1 < CAP) g_csr[(d1 << CAPSH) + p1] = s1;
        if (p2 < CAP) g_csr[(d2 << CAPSH) + p2] = s2;
        if (p3 < CAP) g_csr[(d3 << CAPSH) + p3] = s3;
    } else {
        for (int idx = threadIdx.x; idx < 56 * 16; idx += blockDim.x) {
            sWl[idx] = Wl[idx];
            sWr[idx] = Wr[idx];
        }
        if (threadIdx.x < 16) sb[threadIdx.x] = bl[threadIdx.x];
        __syncthreads();
        int i = (blockIdx.x - FILL_BLOCKS) * blockDim.x + threadIdx.x;
        if (i >= NN) return;
        float al[16], ar[16];
#pragma unroll
        for (int j = 0; j < 16; j++) { al[j] = 0.f; ar[j] = sb[j]; }
#pragma unroll 2
        for (int k = 0; k < 56; k++) {
            float hv = x[(size_t)i * 56 + k];
#pragma unroll
            for (int j = 0; j < 16; j++) {
                al[j] += hv * sWl[k * 16 + j];
                ar[j] += hv * sWr[k * 16 + j];
            }
        }
#pragma unroll
        for (int j = 0; j < 16; j++) {
            g_tbuf[(size_t)i * 16 + j] = al[j];
            g_rbuf[(size_t)i * 16 + j] = ar[j];
        }
    }
}

// ---------------- gather cores (paired-slot, MLP 2) ----------------

__device__ __forceinline__ float4 gather16_core(const float* __restrict__ h,
                                                int gw, int lane, int degc) {
    int c4 = lane & 3;
    int slot = lane >> 2;
    int s0 = gw << CAPSH;
    float4 acc = make_float4(0.f, 0.f, 0.f, 0.f);
    int lim = min(degc, 32);
    int si = (lane < lim) ? g_csr[s0 + lane] : 0;
    for (int jb = 0; jb < lim; jb += 16) {
        int j0 = jb + slot;
        int j1 = jb + 8 + slot;
        int sA = __shfl_sync(0xffffffffu, si, j0);
        int sB = __shfl_sync(0xffffffffu, si, j1);
        if (j0 < lim) {
            float4 v = *reinterpret_cast<const float4*>(h + (size_t)sA * 16 + c4 * 4);
            acc.x += v.x; acc.y += v.y; acc.z += v.z; acc.w += v.w;
        }
        if (j1 < lim) {
            float4 v = *reinterpret_cast<const float4*>(h + (size_t)sB * 16 + c4 * 4);
            acc.x += v.x; acc.y += v.y; acc.z += v.z; acc.w += v.w;
        }
    }
    if (degc > 32) {
        int lim2 = degc - 32;
        int si2 = (lane < lim2) ? g_csr[s0 + 32 + lane] : 0;
        for (int jb = 0; jb < lim2; jb += 16) {
            int j0 = jb + slot;
            int j1 = jb + 8 + slot;
            int sA = __shfl_sync(0xffffffffu, si2, j0);
            int sB = __shfl_sync(0xffffffffu, si2, j1);
            if (j0 < lim2) {
                float4 v = *reinterpret_cast<const float4*>(h + (size_t)sA * 16 + c4 * 4);
                acc.x += v.x; acc.y += v.y; acc.z += v.z; acc.w += v.w;
            }
            if (j1 < lim2) {
                float4 v = *reinterpret_cast<const float4*>(h + (size_t)sB * 16 + c4 * 4);
                acc.x += v.x; acc.y += v.y; acc.z += v.z; acc.w += v.w;
            }
        }
    }
#pragma unroll
    for (int m = 4; m < 32; m <<= 1) {
        acc.x += __shfl_xor_sync(0xffffffffu, acc.x, m);
        acc.y += __shfl_xor_sync(0xffffffffu, acc.y, m);
        acc.z += __shfl_xor_sync(0xffffffffu, acc.z, m);
        acc.w += __shfl_xor_sync(0xffffffffu, acc.w, m);
    }
    return acc;
}

__device__ __forceinline__ float4 gather32_core(const float* __restrict__ h,
                                                int gw, int lane, int degc) {
    int c4 = lane & 7;
    int slot = lane >> 3;
    int s0 = gw << CAPSH;
    float4 acc = make_float4(0.f, 0.f, 0.f, 0.f);
    int lim = min(degc, 32);
    int si = (lane < lim) ? g_csr[s0 + lane] : 0;
    for (int jb = 0; jb < lim; jb += 8) {
        int j0 = jb + slot;
        int j1 = jb + 4 + slot;
        int sA = __shfl_sync(0xffffffffu, si, j0);
        int sB = __shfl_sync(0xffffffffu, si, j1);
        if (j0 < lim) {
            float4 v = *reinterpret_cast<const float4*>(h + (size_t)sA * 32 + c4 * 4);
            acc.x += v.x; acc.y += v.y; acc.z += v.z; acc.w += v.w;
        }
        if (j1 < lim) {
            float4 v = *reinterpret_cast<const float4*>(h + (size_t)sB * 32 + c4 * 4);
            acc.x += v.x; acc.y += v.y; acc.z += v.z; acc.w += v.w;
        }
    }
    if (degc > 32) {
        int lim2 = degc - 32;
        int si2 = (lane < lim2) ? g_csr[s0 + 32 + lane] : 0;
        for (int jb = 0; jb < lim2; jb += 8) {
            int j0 = jb + slot;
            int j1 = jb + 4 + slot;
            int sA = __shfl_sync(0xffffffffu, si2, j0);
            int sB = __shfl_sync(0xffffffffu, si2, j1);
            if (j0 < lim2) {
                float4 v = *reinterpret_cast<const float4*>(h + (size_t)sA * 32 + c4 * 4);
                acc.x += v.x; acc.y += v.y; acc.z += v.z; acc.w += v.w;
            }
            if (j1 < lim2) {
                float4 v = *reinterpret_cast<const float4*>(h + (size_t)sB * 32 + c4 * 4);
                acc.x += v.x; acc.y += v.y; acc.z += v.z; acc.w += v.w;
            }
        }
    }
#pragma unroll
    for (int m = 8; m < 32; m <<= 1) {
        acc.x += __shfl_xor_sync(0xffffffffu, acc.x, m);
        acc.y += __shfl_xor_sync(0xffffffffu, acc.y, m);
        acc.z += __shfl_xor_sync(0xffffffffu, acc.z, m);
        acc.w += __shfl_xor_sync(0xffffffffu, acc.w, m);
    }
    return acc;
}

// ---------------- L0 gather (pre, W=16): bufA = relu(agg/deg + r0) ----------------

__global__ void k_g16pre() {
    int gw = (blockIdx.x * blockDim.x + threadIdx.x) >> 5;
    if (gw >= NN) return;
    int lane = threadIdx.x & 31;
    int deg = g_pos[gw];
    float4 acc = gather16_core(g_tbuf, gw, lane, min(deg, CAP));
    if (lane < 4) {
        int c4 = lane;
        float inv = 1.f / fmaxf((float)deg, 1.f);
        float4 rv = *reinterpret_cast<const float4*>(g_rbuf + (size_t)gw * 16 + c4 * 4);
        float4 o;
        o.x = fmaxf(acc.x * inv + rv.x, 0.f);
        o.y = fmaxf(acc.y * inv + rv.y, 0.f);
        o.z = fmaxf(acc.z * inv + rv.z, 0.f);
        o.w = fmaxf(acc.w * inv + rv.w, 0.f);
        *reinterpret_cast<float4*>(g_bufA + (size_t)gw * 16 + c4 * 4) = o;
    }
}

// ---------------- L1 gather-only ----------------

__global__ void k_g16agg() {
    int gw = (blockIdx.x * blockDim.x + threadIdx.x) >> 5;
    if (gw >= NN) return;
    int lane = threadIdx.x & 31;
    float4 acc = gather16_core(g_bufA, gw, lane, min(g_pos[gw], CAP));
    if (lane < 4)
        *reinterpret_cast<float4*>(g_agg + (size_t)gw * 16 + lane * 4) = acc;
}

// ---------------- L1 update: smem-staged, 2 threads/node x 16 outputs (KEPT: measured win) ----------------

__global__ void __launch_bounds__(256) k_update1(const float* __restrict__ Wl,
                                                 const float* __restrict__ bl,
                                                 const float* __restrict__ Wr) {
    __shared__ float sWl[16 * 32];
    __shared__ float sWr[16 * 32];
    __shared__ float sb[32];
    __shared__ float sAgg[128 * 17];
    __shared__ float sH[128 * 17];
    for (int idx = threadIdx.x; idx < 16 * 32; idx += 256) {
        sWl[idx] = Wl[idx];
        sWr[idx] = Wr[idx];
    }
    if (threadIdx.x < 32) sb[threadIdx.x] = bl[threadIdx.x];
    int nb0 = blockIdx.x * 128;
    for (int idx = threadIdx.x; idx < 128 * 16; idx += 256) {
        int node = idx >> 4, k = idx & 15;
        size_t gidx = (size_t)(nb0 + node) * 16 + k;
        bool ok = (nb0 + node) < NN;
        sAgg[node * 17 + k] = ok ? g_agg[gidx] : 0.f;
        sH[node * 17 + k] = ok ? g_bufA[gidx] : 0.f;
    }
    __syncthreads();
    int nl = threadIdx.x >> 1;        // local node 0..127
    int sub = threadIdx.x & 1;        // output half
    int i = nb0 + nl;
    if (i >= NN) return;
    float inv = 1.f / fmaxf((float)g_pos[i], 1.f);
    float acc[16];
#pragma unroll
    for (int j = 0; j < 16; j++) acc[j] = sb[sub * 16 + j];
#pragma unroll 4
    for (int k = 0; k < 16; k++) {
        float a = sAgg[nl * 17 + k] * inv;
        float hv = sH[nl * 17 + k];
#pragma unroll
        for (int j = 0; j < 16; j++)
            acc[j] += a * sWl[k * 32 + sub * 16 + j] + hv * sWr[k * 32 + sub * 16 + j];
    }
    float* outp = g_bufB + (size_t)i * 32 + sub * 16;
#pragma unroll
    for (int j4 = 0; j4 < 4; j4++) {
        float4 o;
        o.x = fmaxf(acc[j4 * 4 + 0], 0.f);
        o.y = fmaxf(acc[j4 * 4 + 1], 0.f);
        o.z = fmaxf(acc[j4 * 4 + 2], 0.f);
        o.w = fmaxf(acc[j4 * 4 + 3], 0.f);
        *reinterpret_cast<float4*>(outp + j4 * 4) = o;
    }
}

// ---------------- L2 gather-only ----------------

__global__ void k_g32agg() {
    int gw = (blockIdx.x * blockDim.x + threadIdx.x) >> 5;
    if (gw >= NN) return;
    int lane = threadIdx.x & 31;
    float4 acc = gather32_core(g_bufB, gw, lane, min(g_pos[gw], CAP));
    if (lane < 8)
        *reinterpret_cast<float4*>(g_agg + (size_t)gw * 32 + lane * 4) = acc;
}

// ---------------- L2 update: REVERTED to Round-14 thread-per-node + fused L3 prep + pool-zero ----------------

__global__ void __launch_bounds__(128) k_update2(const float* __restrict__ Wl,
                                                 const float* __restrict__ bl,
                                                 const float* __restrict__ Wr,
                                                 const float* __restrict__ Wl3,
                                                 const float* __restrict__ bl3,
                                                 const float* __restrict__ Wr3) {
    __shared__ float sWl[32 * 64];
    __shared__ float sWr[32 * 64];
    __shared__ float sb[64];
    __shared__ float sWl3[64 * 2];
    __shared__ float sWr3[64 * 2];
    __shared__ float sb3[2];
    for (int idx = threadIdx.x; idx < 32 * 64; idx += blockDim.x) {
        sWl[idx] = Wl[idx];
        sWr[idx] = Wr[idx];
    }
    if (threadIdx.x < 64) sb[threadIdx.x] = bl[threadIdx.x];
    if (threadIdx.x < 128) { sWl3[threadIdx.x] = Wl3[threadIdx.x]; sWr3[threadIdx.x] = Wr3[threadIdx.x]; }
    if (threadIdx.x < 2) sb3[threadIdx.x] = bl3[threadIdx.x];
    if (blockIdx.x == 0) {
        for (int idx = threadIdx.x; idx < NG * 2; idx += blockDim.x) g_pool[idx] = 0.f;
        for (int idx = threadIdx.x; idx < NG; idx += blockDim.x) g_gcnt[idx] = 0.f;
    }
    __syncthreads();
    int i = blockIdx.x * blockDim.x + threadIdx.x;
    if (i >= NN) return;
    float inv = 1.f / fmaxf((float)g_pos[i], 1.f);
    float t3p0 = 0.f, t3p1 = 0.f, r3p0 = 0.f, r3p1 = 0.f;
    for (int half = 0; half < 2; half++) {
        float acc[32];
#pragma unroll
        for (int j = 0; j < 32; j++) acc[j] = sb[half * 32 + j];
#pragma unroll 2
        for (int k = 0; k < 32; k++) {
            float a = g_agg[(size_t)i * 32 + k] * inv;
            float hv = g_bufB[(size_t)i * 32 + k];
#pragma unroll
            for (int j = 0; j < 32; j++)
                acc[j] += a * sWl[k * 64 + half * 32 + j] + hv * sWr[k * 64 + half * 32 + j];
        }
#pragma unroll
        for (int j = 0; j < 32; j++) {
            float h3 = fmaxf(acc[j], 0.f);
            int ch = half * 32 + j;
            t3p0 += h3 * sWl3[ch * 2 + 0];
            t3p1 += h3 * sWl3[ch * 2 + 1];
            r3p0 += h3 * sWr3[ch * 2 + 0];
            r3p1 += h3 * sWr3[ch * 2 + 1];
        }
    }
    reinterpret_cast<float2*>(g_tbuf)[i] = make_float2(t3p0, t3p1);
    reinterpret_cast<float2*>(g_rbuf)[i] = make_float2(r3p0 + sb3[0], r3p1 + sb3[1]);
}

// ---------------- L3 gather + pool (2 nodes/warp) + g_pos reset + last-block softmax ----------------

__global__ void __launch_bounds__(256) k_g2pool(const int* __restrict__ batch,
                                                float* __restrict__ out,
                                                int nblocks) {
    int w = (blockIdx.x * blockDim.x + threadIdx.x) >> 5;
    int lane = threadIdx.x & 31;
    int half = lane >> 4;
    int sub = lane & 15;
    int gw = w * 2 + half;
    float ax = 0.f, ay = 0.f;
    int deg = 0;
    if (gw < NN) {
        deg = g_pos[gw];
        int degc = min(deg, CAP);
        int s0 = gw << CAPSH;
        const float2* tv = reinterpret_cast<const float2*>(g_tbuf);
        for (int e = sub; e < degc; e += 16) {
            float2 v = tv[g_csr[s0 + e]];
            ax += v.x; ay += v.y;
        }
    }
#pragma unroll
    for (int m = 1; m < 16; m <<= 1) {
        ax += __shfl_xor_sync(0xffffffffu, ax, m);
        ay += __shfl_xor_sync(0xffffffffu, ay, m);
    }
    if (gw < NN && sub == 0) {
        g_pos[gw] = 0;  // reset degree counter for the next call
        float inv = 1.f / fmaxf((float)deg, 1.f);
        float2 rv = reinterpret_cast<const float2*>(g_rbuf)[gw];
        float hx = fmaxf(ax * inv + rv.x, 0.f);
        float hy = fmaxf(ay * inv + rv.y, 0.f);
        int g = batch[gw];
        atomicAdd(&g_pool[2 * g + 0], hx);
        atomicAdd(&g_pool[2 * g + 1], hy);
        atomicAdd(&g_gcnt[g], 1.f);
    }
    __shared__ int last;
    __syncthreads();
    if (threadIdx.x == 0) {
        __threadfence();
        int v = atomicAdd(&g_done, 1);
        last = (v == nblocks - 1) ? 1 : 0;
    }
    __syncthreads();
    if (last) {
        __threadfence();
        int g = threadIdx.x;
        if (g < NG) {
            float c = fmaxf(g_gcnt[g], 1.f);
            float a = g_pool[2 * g + 0] / c;
            float b = g_pool[2 * g + 1] / c;
            float m = fmaxf(a, b);
            float ea = expf(a - m);
            float eb = expf(b - m);
            float s = ea + eb;
            out[2 * g + 0] = ea / s;
            out[2 * g + 1] = eb / s;
        }
        if (threadIdx.x == 0) g_done = 0;
    }
}

extern "C" void kernel_launch(void* const* d_in, const int* in_sizes, int n_in,
                              void* d_out, int out_size) {
    const float* x = (const float*)d_in[0];
    const int* ei = (const int*)d_in[1];
    const int* batch = (const int*)d_in[2];
    const float* Wl0 = (const float*)d_in[3];
    const float* bl0 = (const float*)d_in[4];
    const float* Wr0 = (const float*)d_in[5];
    const float* Wl1 = (const float*)d_in[6];
    const float* bl1 = (const float*)d_in[7];
    const float* Wr1 = (const float*)d_in[8];
    const float* Wl2 = (const float*)d_in[9];
    const float* bl2 = (const float*)d_in[10];
    const float* Wr2 = (const float*)d_in[11];
    const float* Wl3 = (const float*)d_in[12];
    const float* bl3 = (const float*)d_in[13];
    const float* Wr3 = (const float*)d_in[14];
    float* out = (float*)d_out;

    const int* src = ei;
    const int* dst = ei + NE;

    const int TB = 256;
    auto nb = [](long n, int tb) { return (int)((n + tb - 1) / tb); };
    const int GATHER_GRID = nb((long)NN * 32, TB);       // warp per node (12500)
    const int POOL_GRID = nb((long)NN * 16, TB);         // 2 nodes per warp (6250)

    // 1. fused CSR build + L0 prep
    k_fillprep<<<FILL_BLOCKS + PREP_BLOCKS, TB>>>(src, dst, x, Wl0, bl0, Wr0);
    // 2. L0 gather (pre)
    k_g16pre<<<GATHER_GRID, TB>>>();
    // 3. L1 gather-only
    k_g16agg<<<GATHER_GRID, TB>>>();
    // 4. L1 update (smem-staged, 2 threads/node) — kept
    k_update1<<<nb(NN, 128), TB>>>(Wl1, bl1, Wr1);
    // 5. L2 gather-only
    k_g32agg<<<GATHER_GRID, TB>>>();
    // 6. L2 update (thread-per-node, Round-14 version) + fused L3 prep + pool-zero
    k_update2<<<nb(NN, 128), 128>>>(Wl2, bl2, Wr2, Wl3, bl3, Wr3);
    // 7. L3 gather + pool + softmax
    k_g2pool<<<POOL_GRID, TB>>>(batch, out, POOL_GRID);
}